// round 4
// baseline (speedup 1.0000x reference)
#include <cuda_runtime.h>
#include <math.h>

#define NN 4096
#define DD 128
#define HH 4
#define NMID 9

typedef unsigned long long u64;

// packed 2-lane fp32 FMA: d = a*b + c (elementwise on {lo,hi})
__device__ __forceinline__ u64 ffma2(u64 a, u64 b, u64 c) {
    u64 d;
    asm("fma.rn.f32x2 %0, %1, %2, %3;" : "=l"(d) : "l"(a), "l"(b), "l"(c));
    return d;
}
__device__ __forceinline__ u64 pk2(float x) {
    u64 d;
    asm("mov.b64 %0, {%1, %1};" : "=l"(d) : "f"(x));
    return d;
}

// Scratch (device globals: no allocation allowed). 16B-aligned for float4 access.
__device__ __align__(16) float g_X0[NN * 512];
__device__ __align__(16) float g_X1[NN * 512];
__device__ __align__(16) float g_Wh[HH * NN * DD];
__device__ float g_f1[HH * NN];
__device__ float g_f2[HH * NN];
__device__ float g_m[HH * NN];
__device__ float g_si[HH * NN];
__device__ unsigned g_mask[NN * 128];  // 4096 bits per row = 128 words

// ---------------------------------------------------------------------------
// adj > 0 -> bitmask (2MB, lives in L2 for the whole pipeline)
// ---------------------------------------------------------------------------
__global__ void build_mask_kernel(const float* __restrict__ adj,
                                  unsigned* __restrict__ mask) {
    int i = blockIdx.x;
    int t = threadIdx.x;
    int lane = t & 31;
    const float* row = adj + (size_t)i * NN;
    for (int word = t >> 5; word < 128; word += 8) {
        float v = row[word * 32 + lane];
        unsigned b = __ballot_sync(0xffffffffu, v > 0.f);
        if (lane == 0) mask[i * 128 + word] = b;
    }
}

// ---------------------------------------------------------------------------
// head_relation_combined = entity_emb[head] + relation_emb[relation]
// ---------------------------------------------------------------------------
__global__ void hrc_kernel(const int* __restrict__ head, const int* __restrict__ rel,
                           const float* __restrict__ ee, const float* __restrict__ re,
                           float* __restrict__ out) {
    int i = blockIdx.x;
    int d = threadIdx.x;
    out[(size_t)i * 128 + d] =
        ee[(size_t)head[i] * 128 + d] + re[(size_t)rel[i] * 128 + d];
}

// ---------------------------------------------------------------------------
// Wh[h] = X @ W[h]   (M=4096, N=128, K=Fin), block tile 64x128, 256 threads
// FFMA2 inner loop.
// ---------------------------------------------------------------------------
__global__ void gemm_xw_kernel(const float* __restrict__ X, const float* __restrict__ W,
                               float* __restrict__ Wh, int Fin) {
    int h = blockIdx.z;
    int row0 = blockIdx.x * 64;
    const float* Wp = W + (size_t)h * Fin * 128;
    float* outp = Wh + (size_t)h * NN * 128;

    __shared__ float Xs[64][32];
    __shared__ float Ws[32][128];

    int t = threadIdx.x;
    int tx = t & 31, ty = t >> 5;
    u64 acc2[8][2] = {};

    for (int k0 = 0; k0 < Fin; k0 += 32) {
        __syncthreads();
        // Xs: 64x32 floats = 512 float4
#pragma unroll
        for (int l = 0; l < 2; l++) {
            int idx = t + l * 256;
            int r = idx >> 3;
            int c4 = idx & 7;
            *(float4*)&Xs[r][c4 * 4] =
                *(const float4*)&X[(size_t)(row0 + r) * Fin + k0 + c4 * 4];
        }
        // Ws: 32x128 floats = 1024 float4
#pragma unroll
        for (int l = 0; l < 4; l++) {
            int idx = t + l * 256;
            int r = idx >> 5;
            int c4 = idx & 31;
            *(float4*)&Ws[r][c4 * 4] =
                *(const float4*)&Wp[(size_t)(k0 + r) * 128 + c4 * 4];
        }
        __syncthreads();
#pragma unroll
        for (int k = 0; k < 32; k++) {
            u64 blo = *(const u64*)&Ws[k][tx * 4];
            u64 bhi = *(const u64*)&Ws[k][tx * 4 + 2];
#pragma unroll
            for (int r = 0; r < 8; r++) {
                u64 a2 = pk2(Xs[ty * 8 + r][k]);
                acc2[r][0] = ffma2(a2, blo, acc2[r][0]);
                acc2[r][1] = ffma2(a2, bhi, acc2[r][1]);
            }
        }
    }
#pragma unroll
    for (int r = 0; r < 8; r++) {
        int row = row0 + ty * 8 + r;
        *(u64*)&outp[(size_t)row * 128 + tx * 4] = acc2[r][0];
        *(u64*)&outp[(size_t)row * 128 + tx * 4 + 2] = acc2[r][1];
    }
}

// ---------------------------------------------------------------------------
// f1[i] = Wh[i,:] . a[0:128];  f2[i] = Wh[i,:] . a[128:256]
// ---------------------------------------------------------------------------
__global__ void compute_f_kernel(const float* __restrict__ Wh, const float* __restrict__ A,
                                 float* __restrict__ f1, float* __restrict__ f2) {
    int h = blockIdx.y;
    int warp = threadIdx.x >> 5, lane = threadIdx.x & 31;
    int i = blockIdx.x * 8 + warp;
    const float* row = Wh + ((size_t)h * NN + i) * 128;
    const float* a = A + h * 256;
    float s1 = 0.f, s2 = 0.f;
#pragma unroll
    for (int d = lane; d < 128; d += 32) {
        float v = row[d];
        s1 += v * a[d];
        s2 += v * a[128 + d];
    }
#pragma unroll
    for (int o = 16; o; o >>= 1) {
        s1 += __shfl_xor_sync(0xffffffffu, s1, o);
        s2 += __shfl_xor_sync(0xffffffffu, s2, o);
    }
    if (lane == 0) {
        f1[h * NN + i] = s1;
        f2[h * NN + i] = s2;
    }
}

// ---------------------------------------------------------------------------
// Per-row softmax stats: m = max_j(masked e_ij), si = 1/sum exp(e-m)
// ---------------------------------------------------------------------------
__global__ void stats_kernel(const float* __restrict__ f1, const float* __restrict__ f2,
                             const unsigned* __restrict__ mask,
                             float* __restrict__ mo, float* __restrict__ sio) {
    int h = blockIdx.y;
    int rowbase = blockIdx.x * 16;
    __shared__ float f2s[NN];
    __shared__ unsigned mws[16][128];
    int t = threadIdx.x;
    for (int j = t; j < NN; j += 256) f2s[j] = f2[h * NN + j];
    for (int idx = t; idx < 16 * 128; idx += 256) {
        int r = idx >> 7, w = idx & 127;
        mws[r][w] = mask[(size_t)(rowbase + r) * 128 + w];
    }
    __syncthreads();
    int warp = t >> 5, lane = t & 31;
    for (int rr = warp; rr < 16; rr += 8) {
        int i = rowbase + rr;
        float fr = f1[h * NN + i];
        float mmax = -1e30f;
        for (int w = 0; w < 128; w++) {
            unsigned msk = mws[rr][w];
            if ((msk >> lane) & 1u) {
                float e = fr + f2s[w * 32 + lane];
                e = e > 0.f ? e : 0.2f * e;
                mmax = fmaxf(mmax, e);
            }
        }
#pragma unroll
        for (int o = 16; o; o >>= 1)
            mmax = fmaxf(mmax, __shfl_xor_sync(0xffffffffu, mmax, o));
        float s = 0.f;
        for (int w = 0; w < 128; w++) {
            unsigned msk = mws[rr][w];
            if ((msk >> lane) & 1u) {
                float e = fr + f2s[w * 32 + lane];
                e = e > 0.f ? e : 0.2f * e;
                s += __expf(e - mmax);
            }
        }
#pragma unroll
        for (int o = 16; o; o >>= 1) s += __shfl_xor_sync(0xffffffffu, s, o);
        if (lane == 0) {
            mo[h * NN + i] = mmax;
            sio[h * NN + i] = 1.f / s;
        }
    }
}

// ---------------------------------------------------------------------------
// out_tile[64x128] = softmax_row(e) @ Wh, p generated on the fly (rank-1 + mask),
// elu epilogue. FFMA2 inner loop; P stored duplicated {p,p} for packed LDS.
// ---------------------------------------------------------------------------
__global__ void attn_kernel(const float* __restrict__ Wh, const float* __restrict__ f1,
                            const float* __restrict__ f2, const float* __restrict__ mvec,
                            const float* __restrict__ sivec, const unsigned* __restrict__ mask,
                            float* __restrict__ out, int out_stride) {
    int h = blockIdx.z;
    int row0 = blockIdx.x * 64;
    const float* Whh = Wh + (size_t)h * NN * 128;

    __shared__ float Whs[32][128];
    __shared__ float2 Ps2[64][32];   // duplicated {p,p}
    __shared__ float f1s[64], ms[64], sis[64];
    __shared__ unsigned mw[64];
    __shared__ float f2s[32];

    int t = threadIdx.x, tx = t & 31, ty = t >> 5;
    if (t < 64) {
        f1s[t] = f1[h * NN + row0 + t];
        ms[t] = mvec[h * NN + row0 + t];
        sis[t] = sivec[h * NN + row0 + t];
    }
    u64 acc2[8][2] = {};

    for (int k0 = 0; k0 < NN; k0 += 32) {
        __syncthreads();  // protect tiles from previous iter's readers
        // Whs: 32x128 floats = 1024 float4
#pragma unroll
        for (int l = 0; l < 4; l++) {
            int idx = t + l * 256;
            int r = idx >> 5, c4 = idx & 31;
            *(float4*)&Whs[r][c4 * 4] =
                *(const float4*)&Whh[(size_t)(k0 + r) * 128 + c4 * 4];
        }
        if (t < 32) f2s[t] = f2[h * NN + k0 + t];
        if (t < 64) mw[t] = mask[(size_t)(row0 + t) * 128 + (k0 >> 5)];
        __syncthreads();
        // generate P tile (duplicated): lane tx = column, rows ty + 8e
        {
            float f2v = f2s[tx];
#pragma unroll
            for (int e8 = 0; e8 < 8; e8++) {
                int r = ty + 8 * e8;
                unsigned w = mw[r];
                float ev = f1s[r] + f2v;
                ev = ev > 0.f ? ev : 0.2f * ev;
                float p = ((w >> tx) & 1u) ? __expf(ev - ms[r]) * sis[r] : 0.f;
                Ps2[r][tx] = make_float2(p, p);
            }
        }
        __syncthreads();  // P written column-per-thread, read row-per-thread
#pragma unroll
        for (int k = 0; k < 32; k++) {
            u64 blo = *(const u64*)&Whs[k][tx * 4];
            u64 bhi = *(const u64*)&Whs[k][tx * 4 + 2];
#pragma unroll
            for (int r = 0; r < 8; r++) {
                u64 p2 = *(const u64*)&Ps2[ty * 8 + r][k];
                acc2[r][0] = ffma2(p2, blo, acc2[r][0]);
                acc2[r][1] = ffma2(p2, bhi, acc2[r][1]);
            }
        }
    }
    // elu epilogue + concat write
#pragma unroll
    for (int r = 0; r < 8; r++) {
        int row = row0 + ty * 8 + r;
        float va[4];
        *(u64*)&va[0] = acc2[r][0];
        *(u64*)&va[2] = acc2[r][1];
#pragma unroll
        for (int c = 0; c < 4; c++) {
            float v = va[c];
            v = v > 0.f ? v : expm1f(v);
            out[(size_t)row * out_stride + h * 128 + tx * 4 + c] = v;
        }
    }
}

// ---------------------------------------------------------------------------
extern "C" void kernel_launch(void* const* d_in, const int* in_sizes, int n_in,
                              void* d_out, int out_size) {
    const int* head = (const int*)d_in[0];
    const int* rel = (const int*)d_in[1];
    const float* adj = (const float*)d_in[2];
    const float* ee = (const float*)d_in[3];
    const float* re = (const float*)d_in[4];
    const float* W0 = (const float*)d_in[5];
    const float* a0 = (const float*)d_in[6];
    const float* Wm = (const float*)d_in[7];
    const float* am = (const float*)d_in[8];
    const float* Wo = (const float*)d_in[9];
    const float* ao = (const float*)d_in[10];
    float* out = (float*)d_out;

    float *X0, *X1, *Wh, *f1, *f2, *mv, *si;
    unsigned* mask;
    cudaGetSymbolAddress((void**)&X0, g_X0);
    cudaGetSymbolAddress((void**)&X1, g_X1);
    cudaGetSymbolAddress((void**)&Wh, g_Wh);
    cudaGetSymbolAddress((void**)&f1, g_f1);
    cudaGetSymbolAddress((void**)&f2, g_f2);
    cudaGetSymbolAddress((void**)&mv, g_m);
    cudaGetSymbolAddress((void**)&si, g_si);
    cudaGetSymbolAddress((void**)&mask, g_mask);

    build_mask_kernel<<<NN, 256>>>(adj, mask);
    hrc_kernel<<<NN, 128>>>(head, rel, ee, re, out + (size_t)NN * 128);

    // layer 0: D -> H*D
    gemm_xw_kernel<<<dim3(64, 1, HH), 256>>>(ee, W0, Wh, 128);
    compute_f_kernel<<<dim3(512, HH), 256>>>(Wh, a0, f1, f2);
    stats_kernel<<<dim3(256, HH), 256>>>(f1, f2, mask, mv, si);
    attn_kernel<<<dim3(64, 1, HH), 256>>>(Wh, f1, f2, mv, si, mask, X0, 512);

    // 9 middle layers: H*D -> H*D (ping-pong X0/X1)
    float* cur = X0;
    float* nxt = X1;
    for (int l = 0; l < NMID; l++) {
        gemm_xw_kernel<<<dim3(64, 1, HH), 256>>>(cur, Wm + (size_t)l * HH * 512 * 128, Wh, 512);
        compute_f_kernel<<<dim3(512, HH), 256>>>(Wh, am + (size_t)l * HH * 256, f1, f2);
        stats_kernel<<<dim3(256, HH), 256>>>(f1, f2, mask, mv, si);
        attn_kernel<<<dim3(64, 1, HH), 256>>>(Wh, f1, f2, mv, si, mask, nxt, 512);
        float* tmp = cur; cur = nxt; nxt = tmp;
    }

    // output layer: single head H*D -> D, elu, write to d_out[0 : 4096*128]
    gemm_xw_kernel<<<dim3(64, 1, 1), 256>>>(cur, Wo, Wh, 512);
    compute_f_kernel<<<dim3(512, 1), 256>>>(Wh, ao, f1, f2);
    stats_kernel<<<dim3(256, 1), 256>>>(f1, f2, mask, mv, si);
    attn_kernel<<<dim3(64, 1, 1), 256>>>(Wh, f1, f2, mv, si, mask, out, 128);
}

// round 6
// speedup vs baseline: 1.7626x; 1.7626x over previous
#include <cuda_runtime.h>
#include <cuda_bf16.h>
#include <math.h>
#include <cstdint>

#define NN 4096
#define DD 128
#define HH 4
#define NMID 9

typedef unsigned long long u64;

// ===========================================================================
// warp-mma helpers (sm_80-class PTX: compiles for plain sm_103)
// ===========================================================================
__device__ __forceinline__ uint32_t smem_u32(const void* p) {
    uint32_t a;
    asm("{ .reg .u64 t; cvta.to.shared.u64 t, %1; cvt.u32.u64 %0, t; }" : "=r"(a) : "l"(p));
    return a;
}
__device__ __forceinline__ void ldsm_x4(unsigned* r, uint32_t addr) {
    asm volatile("ldmatrix.sync.aligned.m8n8.x4.shared.b16 {%0,%1,%2,%3}, [%4];"
                 : "=r"(r[0]), "=r"(r[1]), "=r"(r[2]), "=r"(r[3]) : "r"(addr));
}
__device__ __forceinline__ void mma_bf16(float* d, const unsigned* a, const unsigned* b) {
    asm volatile(
        "mma.sync.aligned.m16n8k16.row.col.f32.bf16.bf16.f32 "
        "{%0,%1,%2,%3}, {%4,%5,%6,%7}, {%8,%9}, {%0,%1,%2,%3};"
        : "+f"(d[0]), "+f"(d[1]), "+f"(d[2]), "+f"(d[3])
        : "r"(a[0]), "r"(a[1]), "r"(a[2]), "r"(a[3]), "r"(b[0]), "r"(b[1]));
}

// ===========================================================================
// Scratch (device globals)
// ===========================================================================
__device__ __align__(16) float g_X0[NN * 512];
__device__ __align__(16) float g_X1[NN * 512];
__device__ __align__(16) float g_Wh[HH * NN * DD];
__device__ __align__(16) __nv_bfloat16 g_WhT_hi[HH * DD * NN];  // [h][n=128][k=4096]
__device__ __align__(16) __nv_bfloat16 g_WhT_lo[HH * DD * NN];
__device__ float g_f1[HH * NN];
__device__ float g_f2[HH * NN];
__device__ float g_m[HH * NN];
__device__ float g_si[HH * NN];
__device__ __align__(16) float g_rowA[HH * NN];
__device__ __align__(16) float g_rowC[HH * NN];
__device__ __align__(16) float g_colB[HH * NN];
__device__ __align__(16) float g_colD[HH * NN];
__device__ unsigned g_mask[NN * 128];

// ===========================================================================
// adj > 0 -> bitmask
// ===========================================================================
__global__ void build_mask_kernel(const float* __restrict__ adj,
                                  unsigned* __restrict__ mask) {
    int i = blockIdx.x;
    int t = threadIdx.x;
    int lane = t & 31;
    const float* row = adj + (size_t)i * NN;
    for (int word = t >> 5; word < 128; word += 8) {
        float v = row[word * 32 + lane];
        unsigned b = __ballot_sync(0xffffffffu, v > 0.f);
        if (lane == 0) mask[i * 128 + word] = b;
    }
}

__global__ void hrc_kernel(const int* __restrict__ head, const int* __restrict__ rel,
                           const float* __restrict__ ee, const float* __restrict__ re,
                           float* __restrict__ out) {
    int i = blockIdx.x;
    int d = threadIdx.x;
    out[(size_t)i * 128 + d] =
        ee[(size_t)head[i] * 128 + d] + re[(size_t)rel[i] * 128 + d];
}

// ===========================================================================
// Wh[h] = X @ W[h]  (scalar fp32)
// ===========================================================================
__global__ void gemm_xw_kernel(const float* __restrict__ X, const float* __restrict__ W,
                               float* __restrict__ Wh, int Fin) {
    int h = blockIdx.z;
    int row0 = blockIdx.x * 64;
    const float* Wp = W + (size_t)h * Fin * 128;
    float* outp = Wh + (size_t)h * NN * 128;

    __shared__ float Xs[64][32];
    __shared__ float Ws[32][128];

    int t = threadIdx.x;
    int tx = t & 31, ty = t >> 5;
    float acc[8][4] = {};

    for (int k0 = 0; k0 < Fin; k0 += 32) {
        __syncthreads();
#pragma unroll
        for (int l = 0; l < 2; l++) {
            int idx = t + l * 256;
            int r = idx >> 3, c4 = idx & 7;
            *(float4*)&Xs[r][c4 * 4] =
                *(const float4*)&X[(size_t)(row0 + r) * Fin + k0 + c4 * 4];
        }
#pragma unroll
        for (int l = 0; l < 4; l++) {
            int idx = t + l * 256;
            int r = idx >> 5, c4 = idx & 31;
            *(float4*)&Ws[r][c4 * 4] =
                *(const float4*)&Wp[(size_t)(k0 + r) * 128 + c4 * 4];
        }
        __syncthreads();
#pragma unroll
        for (int k = 0; k < 32; k += 4) {
            float4 b0 = *(float4*)&Ws[k + 0][tx * 4];
            float4 b1 = *(float4*)&Ws[k + 1][tx * 4];
            float4 b2 = *(float4*)&Ws[k + 2][tx * 4];
            float4 b3 = *(float4*)&Ws[k + 3][tx * 4];
#pragma unroll
            for (int r = 0; r < 8; r++) {
                float4 a = *(float4*)&Xs[ty * 8 + r][k];
                acc[r][0] = fmaf(a.x, b0.x, acc[r][0]);
                acc[r][1] = fmaf(a.x, b0.y, acc[r][1]);
                acc[r][2] = fmaf(a.x, b0.z, acc[r][2]);
                acc[r][3] = fmaf(a.x, b0.w, acc[r][3]);
                acc[r][0] = fmaf(a.y, b1.x, acc[r][0]);
                acc[r][1] = fmaf(a.y, b1.y, acc[r][1]);
                acc[r][2] = fmaf(a.y, b1.z, acc[r][2]);
                acc[r][3] = fmaf(a.y, b1.w, acc[r][3]);
                acc[r][0] = fmaf(a.z, b2.x, acc[r][0]);
                acc[r][1] = fmaf(a.z, b2.y, acc[r][1]);
                acc[r][2] = fmaf(a.z, b2.z, acc[r][2]);
                acc[r][3] = fmaf(a.z, b2.w, acc[r][3]);
                acc[r][0] = fmaf(a.w, b3.x, acc[r][0]);
                acc[r][1] = fmaf(a.w, b3.y, acc[r][1]);
                acc[r][2] = fmaf(a.w, b3.z, acc[r][2]);
                acc[r][3] = fmaf(a.w, b3.w, acc[r][3]);
            }
        }
    }
#pragma unroll
    for (int r = 0; r < 8; r++) {
        int row = row0 + ty * 8 + r;
#pragma unroll
        for (int c = 0; c < 4; c++)
            outp[(size_t)row * 128 + tx * 4 + c] = acc[r][c];
    }
}

// ===========================================================================
// f1/f2
// ===========================================================================
__global__ void compute_f_kernel(const float* __restrict__ Wh, const float* __restrict__ A,
                                 float* __restrict__ f1, float* __restrict__ f2) {
    int h = blockIdx.y;
    int warp = threadIdx.x >> 5, lane = threadIdx.x & 31;
    int i = blockIdx.x * 8 + warp;
    const float* row = Wh + ((size_t)h * NN + i) * 128;
    const float* a = A + h * 256;
    float s1 = 0.f, s2 = 0.f;
#pragma unroll
    for (int d = lane; d < 128; d += 32) {
        float v = row[d];
        s1 += v * a[d];
        s2 += v * a[128 + d];
    }
#pragma unroll
    for (int o = 16; o; o >>= 1) {
        s1 += __shfl_xor_sync(0xffffffffu, s1, o);
        s2 += __shfl_xor_sync(0xffffffffu, s2, o);
    }
    if (lane == 0) {
        f1[h * NN + i] = s1;
        f2[h * NN + i] = s2;
    }
}

// ===========================================================================
// softmax stats
// ===========================================================================
__global__ void stats_kernel(const float* __restrict__ f1, const float* __restrict__ f2,
                             const unsigned* __restrict__ mask,
                             float* __restrict__ mo, float* __restrict__ sio) {
    int h = blockIdx.y;
    int rowbase = blockIdx.x * 16;
    __shared__ float f2s[NN];
    __shared__ unsigned mws[16][128];
    int t = threadIdx.x;
    for (int j = t; j < NN; j += 256) f2s[j] = f2[h * NN + j];
    for (int idx = t; idx < 16 * 128; idx += 256) {
        int r = idx >> 7, w = idx & 127;
        mws[r][w] = mask[(size_t)(rowbase + r) * 128 + w];
    }
    __syncthreads();
    int warp = t >> 5, lane = t & 31;
    for (int rr = warp; rr < 16; rr += 8) {
        int i = rowbase + rr;
        float fr = f1[h * NN + i];
        float mmax = -1e30f;
        for (int w = 0; w < 128; w++) {
            unsigned msk = mws[rr][w];
            if ((msk >> lane) & 1u) {
                float e = fr + f2s[w * 32 + lane];
                e = e > 0.f ? e : 0.2f * e;
                mmax = fmaxf(mmax, e);
            }
        }
#pragma unroll
        for (int o = 16; o; o >>= 1)
            mmax = fmaxf(mmax, __shfl_xor_sync(0xffffffffu, mmax, o));
        float s = 0.f;
        for (int w = 0; w < 128; w++) {
            unsigned msk = mws[rr][w];
            if ((msk >> lane) & 1u) {
                float e = fr + f2s[w * 32 + lane];
                e = e > 0.f ? e : 0.2f * e;
                s += __expf(e - mmax);
            }
        }
#pragma unroll
        for (int o = 16; o; o >>= 1) s += __shfl_xor_sync(0xffffffffu, s, o);
        if (lane == 0) {
            mo[h * NN + i] = mmax;
            sio[h * NN + i] = 1.f / s;
        }
    }
}

// ===========================================================================
// rowA = si*exp(f1-m), rowC = si*exp(0.2f1-m), colB = exp(f2), colD = exp(0.2f2)
// ===========================================================================
__global__ void prep_vec_kernel(const float* __restrict__ f1, const float* __restrict__ f2,
                                const float* __restrict__ mm, const float* __restrict__ si,
                                float* __restrict__ rowA, float* __restrict__ rowC,
                                float* __restrict__ colB, float* __restrict__ colD) {
    int h = blockIdx.y;
    int i = blockIdx.x * 256 + threadIdx.x;
    int idx = h * NN + i;
    float m = mm[idx], s = si[idx], a = f1[idx], b = f2[idx];
    rowA[idx] = s * __expf(a - m);
    rowC[idx] = s * __expf(0.2f * a - m);
    colB[idx] = __expf(b);
    colD[idx] = __expf(0.2f * b);
}

// ===========================================================================
// WhT split: Wh fp32 [h][4096 k][128 n] -> WhT_hi/lo bf16 [h][128 n][4096 k]
// ===========================================================================
__global__ void wh_split_kernel(const float* __restrict__ Wh,
                                __nv_bfloat16* __restrict__ WhT_hi,
                                __nv_bfloat16* __restrict__ WhT_lo) {
    int h = blockIdx.z;
    int kbase = blockIdx.x * 32;
    int nbase = blockIdx.y * 32;
    __shared__ float ts[32][33];
    const float* src = Wh + (size_t)h * NN * 128;
    int t = threadIdx.x;
#pragma unroll
    for (int l = 0; l < 4; l++) {
        int e = t + l * 256;
        int r = e >> 5, c = e & 31;
        ts[r][c] = src[(size_t)(kbase + r) * 128 + nbase + c];
    }
    __syncthreads();
#pragma unroll
    for (int l = 0; l < 4; l++) {
        int e = t + l * 256;
        int r = e >> 5, c = e & 31;  // r = n-local, c = k-local
        float v = ts[c][r];
        __nv_bfloat16 hi = __float2bfloat16(v);
        __nv_bfloat16 lo = __float2bfloat16(v - __bfloat162float(hi));
        size_t o = (size_t)(h * 128 + nbase + r) * NN + kbase + c;
        WhT_hi[o] = hi;
        WhT_lo[o] = lo;
    }
}

// ===========================================================================
// mma.sync attention: 64-row x 128-col output tile per CTA.
// P (on-the-fly, split bf16 hi/lo) @ WhT (split bf16), 3-pass -> fp32 acc.
// grid (64, H). 256 threads = 8 warps: wr = wid&3 row group, wc = wid>>2 col group.
// ===========================================================================
#define PSTR 40  // bf16 elems per smem row (80B: 16B-aligned, ldmatrix conflict-free)

__global__ void __launch_bounds__(256)
attn_mma_kernel(const __nv_bfloat16* __restrict__ WhT_hi,
                const __nv_bfloat16* __restrict__ WhT_lo,
                const float* __restrict__ rowA, const float* __restrict__ rowC,
                const float* __restrict__ colB, const float* __restrict__ colD,
                const unsigned* __restrict__ mask,
                float* __restrict__ out, int out_stride) {
    __shared__ __align__(16) __nv_bfloat16 Phi[64][PSTR];
    __shared__ __align__(16) __nv_bfloat16 Plo[64][PSTR];
    __shared__ __align__(16) __nv_bfloat16 Bhi[128][PSTR];
    __shared__ __align__(16) __nv_bfloat16 Blo[128][PSTR];

    int h = blockIdx.y;
    int row0 = blockIdx.x * 64;
    int hbase = h * NN;
    int t = threadIdx.x, wid = t >> 5, lane = t & 31;
    int wr = wid & 3, wc = wid >> 2;

    uint32_t sPhi = smem_u32(&Phi[0][0]);
    uint32_t sPlo = smem_u32(&Plo[0][0]);
    uint32_t sBhi = smem_u32(&Bhi[0][0]);
    uint32_t sBlo = smem_u32(&Blo[0][0]);

    // P-gen role: thread covers row pr, k-octet kq
    int pr = t >> 2, kq = t & 3;
    float Ar = rowA[hbase + row0 + pr];
    float Cr = rowC[hbase + row0 + pr];
    const unsigned* mrow = mask + (size_t)(row0 + pr) * 128;

    float d[8][4] = {};

    // ldmatrix lane-address components (bytes)
    uint32_t a_off = (uint32_t)(wr * 16 + ((lane >> 3) & 1) * 8 + (lane & 7)) * (PSTR * 2)
                   + (uint32_t)((lane >> 4) * 8) * 2;
    uint32_t b_roff = (uint32_t)(wc * 64 + (lane >> 4) * 8 + (lane & 7)) * (PSTR * 2);
    uint32_t b_koff = (uint32_t)(((lane >> 3) & 1) * 8) * 2;

    for (int c = 0; c < 128; c++) {
        int k0 = c * 32;
        __syncthreads();  // previous chunk's ldmatrix reads done

        // --- stage WhT hi/lo tiles: 128 n-rows x 32 k ---
#pragma unroll
        for (int l = 0; l < 2; l++) {
            int idx = t + l * 256;
            int n = idx >> 2, q = idx & 3;
            size_t go = (size_t)(h * 128 + n) * NN + k0 + q * 8;
            *(uint4*)&Bhi[n][q * 8] = *(const uint4*)(WhT_hi + go);
            *(uint4*)&Blo[n][q * 8] = *(const uint4*)(WhT_lo + go);
        }

        // --- P-gen: 8 k-values for (row pr, k = k0 + kq*8 ...) ---
        {
            int kb = k0 + kq * 8;
            unsigned w8 = mrow[c] >> (kq * 8);
            float4 b0 = *(const float4*)(colB + hbase + kb);
            float4 b1 = *(const float4*)(colB + hbase + kb + 4);
            float4 d0 = *(const float4*)(colD + hbase + kb);
            float4 d1 = *(const float4*)(colD + hbase + kb + 4);
            float p[8];
            p[0] = (w8 & 1u)   ? fmaxf(Ar * b0.x, Cr * d0.x) : 0.f;
            p[1] = (w8 & 2u)   ? fmaxf(Ar * b0.y, Cr * d0.y) : 0.f;
            p[2] = (w8 & 4u)   ? fmaxf(Ar * b0.z, Cr * d0.z) : 0.f;
            p[3] = (w8 & 8u)   ? fmaxf(Ar * b0.w, Cr * d0.w) : 0.f;
            p[4] = (w8 & 16u)  ? fmaxf(Ar * b1.x, Cr * d1.x) : 0.f;
            p[5] = (w8 & 32u)  ? fmaxf(Ar * b1.y, Cr * d1.y) : 0.f;
            p[6] = (w8 & 64u)  ? fmaxf(Ar * b1.z, Cr * d1.z) : 0.f;
            p[7] = (w8 & 128u) ? fmaxf(Ar * b1.w, Cr * d1.w) : 0.f;
            uint4 uh, ul;
            unsigned* ph = &uh.x;
            unsigned* pl = &ul.x;
#pragma unroll
            for (int j = 0; j < 4; j++) {
                __nv_bfloat162 h2 = __floats2bfloat162_rn(p[2 * j], p[2 * j + 1]);
                float r0 = p[2 * j] - __bfloat162float(h2.x);
                float r1 = p[2 * j + 1] - __bfloat162float(h2.y);
                __nv_bfloat162 l2 = __floats2bfloat162_rn(r0, r1);
                ph[j] = *(unsigned*)&h2;
                pl[j] = *(unsigned*)&l2;
            }
            *(uint4*)&Phi[pr][kq * 8] = uh;
            *(uint4*)&Plo[pr][kq * 8] = ul;
        }
        __syncthreads();  // tiles + P ready

        // --- mma: 2 k16 steps ---
#pragma unroll
        for (int s = 0; s < 2; s++) {
            unsigned ah[4], al[4];
            ldsm_x4(ah, sPhi + a_off + s * 32);
            ldsm_x4(al, sPlo + a_off + s * 32);
#pragma unroll
            for (int pp = 0; pp < 4; pp++) {
                unsigned bh[4], bl[4];
                uint32_t boff = b_roff + (uint32_t)(pp * 16) * (PSTR * 2) + b_koff + s * 32;
                ldsm_x4(bh, sBhi + boff);
                ldsm_x4(bl, sBlo + boff);
                mma_bf16(d[2 * pp],     ah, bh);
                mma_bf16(d[2 * pp + 1], ah, bh + 2);
                mma_bf16(d[2 * pp],     ah, bl);
                mma_bf16(d[2 * pp + 1], ah, bl + 2);
                mma_bf16(d[2 * pp],     al, bh);
                mma_bf16(d[2 * pp + 1], al, bh + 2);
            }
        }
    }

    // --- epilogue: elu + write ---
    int r0 = row0 + wr * 16 + (lane >> 2);
    int cbase = h * 128 + wc * 64 + (lane & 3) * 2;
#pragma unroll
    for (int nt = 0; nt < 8; nt++) {
        int col = cbase + nt * 8;
        float v0 = d[nt][0], v1 = d[nt][1], v2 = d[nt][2], v3 = d[nt][3];
        v0 = v0 > 0.f ? v0 : expm1f(v0);
        v1 = v1 > 0.f ? v1 : expm1f(v1);
        v2 = v2 > 0.f ? v2 : expm1f(v2);
        v3 = v3 > 0.f ? v3 : expm1f(v3);
        *(float2*)&out[(size_t)r0 * out_stride + col] = make_float2(v0, v1);
        *(float2*)&out[(size_t)(r0 + 8) * out_stride + col] = make_float2(v2, v3);
    }
}

// ===========================================================================
extern "C" void kernel_launch(void* const* d_in, const int* in_sizes, int n_in,
                              void* d_out, int out_size) {
    const int* head = (const int*)d_in[0];
    const int* rel = (const int*)d_in[1];
    const float* adj = (const float*)d_in[2];
    const float* ee = (const float*)d_in[3];
    const float* re = (const float*)d_in[4];
    const float* W0 = (const float*)d_in[5];
    const float* a0 = (const float*)d_in[6];
    const float* Wm = (const float*)d_in[7];
    const float* am = (const float*)d_in[8];
    const float* Wo = (const float*)d_in[9];
    const float* ao = (const float*)d_in[10];
    float* out = (float*)d_out;

    float *X0, *X1, *Wh, *f1, *f2, *mv, *si, *rA, *rC, *cB, *cD;
    __nv_bfloat16 *WhTh, *WhTl;
    unsigned* mask;
    cudaGetSymbolAddress((void**)&X0, g_X0);
    cudaGetSymbolAddress((void**)&X1, g_X1);
    cudaGetSymbolAddress((void**)&Wh, g_Wh);
    cudaGetSymbolAddress((void**)&f1, g_f1);
    cudaGetSymbolAddress((void**)&f2, g_f2);
    cudaGetSymbolAddress((void**)&mv, g_m);
    cudaGetSymbolAddress((void**)&si, g_si);
    cudaGetSymbolAddress((void**)&rA, g_rowA);
    cudaGetSymbolAddress((void**)&rC, g_rowC);
    cudaGetSymbolAddress((void**)&cB, g_colB);
    cudaGetSymbolAddress((void**)&cD, g_colD);
    cudaGetSymbolAddress((void**)&WhTh, g_WhT_hi);
    cudaGetSymbolAddress((void**)&WhTl, g_WhT_lo);
    cudaGetSymbolAddress((void**)&mask, g_mask);

    build_mask_kernel<<<NN, 256>>>(adj, mask);
    hrc_kernel<<<NN, 128>>>(head, rel, ee, re, out + (size_t)NN * 128);

    // layer 0
    gemm_xw_kernel<<<dim3(64, 1, HH), 256>>>(ee, W0, Wh, 128);
    compute_f_kernel<<<dim3(512, HH), 256>>>(Wh, a0, f1, f2);
    stats_kernel<<<dim3(256, HH), 256>>>(f1, f2, mask, mv, si);
    prep_vec_kernel<<<dim3(16, HH), 256>>>(f1, f2, mv, si, rA, rC, cB, cD);
    wh_split_kernel<<<dim3(128, 4, HH), 256>>>(Wh, WhTh, WhTl);
    attn_mma_kernel<<<dim3(64, HH), 256>>>(WhTh, WhTl, rA, rC, cB, cD, mask, X0, 512);

    // 9 middle layers
    float* cur = X0;
    float* nxt = X1;
    for (int l = 0; l < NMID; l++) {
        gemm_xw_kernel<<<dim3(64, 1, HH), 256>>>(cur, Wm + (size_t)l * HH * 512 * 128, Wh, 512);
        compute_f_kernel<<<dim3(512, HH), 256>>>(Wh, am + (size_t)l * HH * 256, f1, f2);
        stats_kernel<<<dim3(256, HH), 256>>>(f1, f2, mask, mv, si);
        prep_vec_kernel<<<dim3(16, HH), 256>>>(f1, f2, mv, si, rA, rC, cB, cD);
        wh_split_kernel<<<dim3(128, 4, HH), 256>>>(Wh, WhTh, WhTl);
        attn_mma_kernel<<<dim3(64, HH), 256>>>(WhTh, WhTl, rA, rC, cB, cD, mask, nxt, 512);
        float* tmp = cur; cur = nxt; nxt = tmp;
    }

    // output layer (1 head)
    gemm_xw_kernel<<<dim3(64, 1, 1), 256>>>(cur, Wo, Wh, 512);
    compute_f_kernel<<<dim3(512, 1), 256>>>(Wh, ao, f1, f2);
    stats_kernel<<<dim3(256, 1), 256>>>(f1, f2, mask, mv, si);
    prep_vec_kernel<<<dim3(16, 1), 256>>>(f1, f2, mv, si, rA, rC, cB, cD);
    wh_split_kernel<<<dim3(128, 4, 1), 256>>>(Wh, WhTh, WhTl);
    attn_mma_kernel<<<dim3(64, 1), 256>>>(WhTh, WhTl, rA, rC, cB, cD, mask, out, 128);
}

// round 7
// speedup vs baseline: 2.2316x; 1.2661x over previous
#include <cuda_runtime.h>
#include <cuda_bf16.h>
#include <math.h>
#include <cstdint>

#define NN 4096
#define DD 128
#define HH 4
#define NMID 9
#define PSTR 40  // bf16 elems per smem row (80B, ldmatrix conflict-free)

typedef unsigned long long u64;

// ===========================================================================
// PTX helpers (sm_80-class: compiles for plain sm_103)
// ===========================================================================
__device__ __forceinline__ uint32_t smem_u32(const void* p) {
    uint32_t a;
    asm("{ .reg .u64 t; cvta.to.shared.u64 t, %1; cvt.u32.u64 %0, t; }" : "=r"(a) : "l"(p));
    return a;
}
__device__ __forceinline__ void ldsm_x4(unsigned* r, uint32_t addr) {
    asm volatile("ldmatrix.sync.aligned.m8n8.x4.shared.b16 {%0,%1,%2,%3}, [%4];"
                 : "=r"(r[0]), "=r"(r[1]), "=r"(r[2]), "=r"(r[3]) : "r"(addr));
}
__device__ __forceinline__ void mma_bf16(float* d, const unsigned* a, const unsigned* b) {
    asm volatile(
        "mma.sync.aligned.m16n8k16.row.col.f32.bf16.bf16.f32 "
        "{%0,%1,%2,%3}, {%4,%5,%6,%7}, {%8,%9}, {%0,%1,%2,%3};"
        : "+f"(d[0]), "+f"(d[1]), "+f"(d[2]), "+f"(d[3])
        : "r"(a[0]), "r"(a[1]), "r"(a[2]), "r"(a[3]), "r"(b[0]), "r"(b[1]));
}
__device__ __forceinline__ void cp16(uint32_t dst, const void* src) {
    asm volatile("cp.async.ca.shared.global [%0], [%1], 16;" :: "r"(dst), "l"(src) : "memory");
}
#define CP_COMMIT() asm volatile("cp.async.commit_group;" ::: "memory")
#define CP_WAIT0()  asm volatile("cp.async.wait_group 0;" ::: "memory")

// ===========================================================================
// Scratch (device globals)
// ===========================================================================
__device__ __align__(16) float g_X0[NN * 512];
__device__ __align__(16) float g_X1[NN * 512];
__device__ __align__(16) float g_Wh[HH * NN * DD];
__device__ __align__(16) __nv_bfloat16 g_WhT_hi[HH * DD * NN];  // [h][n=128][k=4096]
__device__ __align__(16) __nv_bfloat16 g_WhT_lo[HH * DD * NN];
__device__ __align__(16) __nv_bfloat16 g_Xhi[NN * 512];
__device__ __align__(16) __nv_bfloat16 g_Xlo[NN * 512];
__device__ __align__(16) __nv_bfloat16 g_Wt_hi[HH * DD * 512];  // [h][n=128][k<=512]
__device__ __align__(16) __nv_bfloat16 g_Wt_lo[HH * DD * 512];
__device__ float g_f1[HH * NN];
__device__ float g_f2[HH * NN];
__device__ float g_m[HH * NN];
__device__ float g_si[HH * NN];
__device__ __align__(16) float g_rowA[HH * NN];
__device__ __align__(16) float g_rowC[HH * NN];
__device__ __align__(16) float g_colB[HH * NN];
__device__ __align__(16) float g_colD[HH * NN];
__device__ unsigned g_mask[NN * 128];

// ===========================================================================
// adj > 0 -> bitmask
// ===========================================================================
__global__ void build_mask_kernel(const float* __restrict__ adj,
                                  unsigned* __restrict__ mask) {
    int i = blockIdx.x;
    int t = threadIdx.x;
    int lane = t & 31;
    const float* row = adj + (size_t)i * NN;
    for (int word = t >> 5; word < 128; word += 8) {
        float v = row[word * 32 + lane];
        unsigned b = __ballot_sync(0xffffffffu, v > 0.f);
        if (lane == 0) mask[i * 128 + word] = b;
    }
}

__global__ void hrc_kernel(const int* __restrict__ head, const int* __restrict__ rel,
                           const float* __restrict__ ee, const float* __restrict__ re,
                           float* __restrict__ out) {
    int i = blockIdx.x;
    int d = threadIdx.x;
    out[(size_t)i * 128 + d] =
        ee[(size_t)head[i] * 128 + d] + re[(size_t)rel[i] * 128 + d];
}

// ===========================================================================
// fp32 -> bf16 hi/lo split (flat)
// ===========================================================================
__global__ void split_kernel(const float* __restrict__ src,
                             __nv_bfloat16* __restrict__ hi,
                             __nv_bfloat16* __restrict__ lo, int n) {
    int i = blockIdx.x * 256 + threadIdx.x;
    if (i < n) {
        float v = src[i];
        __nv_bfloat16 h = __float2bfloat16(v);
        hi[i] = h;
        lo[i] = __float2bfloat16(v - __bfloat162float(h));
    }
}

// ===========================================================================
// transpose + split: src fp32 [h][kdim][128] -> hi/lo bf16 [h][128][kdim]
// grid (kdim/32, 4, H)
// ===========================================================================
__global__ void wt_split_kernel(const float* __restrict__ src,
                                __nv_bfloat16* __restrict__ dhi,
                                __nv_bfloat16* __restrict__ dlo, int kdim) {
    int h = blockIdx.z;
    int kbase = blockIdx.x * 32;
    int nbase = blockIdx.y * 32;
    __shared__ float ts[32][33];
    const float* sp = src + (size_t)h * kdim * 128;
    int t = threadIdx.x;
#pragma unroll
    for (int l = 0; l < 4; l++) {
        int e = t + l * 256;
        int r = e >> 5, c = e & 31;
        ts[r][c] = sp[(size_t)(kbase + r) * 128 + nbase + c];
    }
    __syncthreads();
#pragma unroll
    for (int l = 0; l < 4; l++) {
        int e = t + l * 256;
        int r = e >> 5, c = e & 31;  // r = n-local, c = k-local
        float v = ts[c][r];
        __nv_bfloat16 hi = __float2bfloat16(v);
        __nv_bfloat16 lo = __float2bfloat16(v - __bfloat162float(hi));
        size_t o = (size_t)(h * 128 + nbase + r) * kdim + kbase + c;
        dhi[o] = hi;
        dlo[o] = lo;
    }
}

// ===========================================================================
// Tensorized Wh = X @ W : A = Xhi/lo [m][k], B = Wt hi/lo [h][n=128][k=Fin]
// CTA: 64m x 128n, grid (64, H). Same fragment paths as attn (proven).
// ===========================================================================
__global__ void __launch_bounds__(256)
gemm_mma_kernel(const __nv_bfloat16* __restrict__ Xhi, const __nv_bfloat16* __restrict__ Xlo,
                const __nv_bfloat16* __restrict__ WtHi, const __nv_bfloat16* __restrict__ WtLo,
                float* __restrict__ Wh, int Fin) {
    __shared__ __align__(16) __nv_bfloat16 Ahi[64][PSTR];
    __shared__ __align__(16) __nv_bfloat16 Alo[64][PSTR];
    __shared__ __align__(16) __nv_bfloat16 Bhi[128][PSTR];
    __shared__ __align__(16) __nv_bfloat16 Blo[128][PSTR];

    int h = blockIdx.y;
    int row0 = blockIdx.x * 64;
    int t = threadIdx.x, wid = t >> 5, lane = t & 31;
    int wr = wid & 3, wc = wid >> 2;
    const __nv_bfloat16* Wth = WtHi + (size_t)h * 128 * Fin;
    const __nv_bfloat16* Wtl = WtLo + (size_t)h * 128 * Fin;
    float* outp = Wh + (size_t)h * NN * 128;

    uint32_t sAhi = smem_u32(Ahi), sAlo = smem_u32(Alo);
    uint32_t sBhi = smem_u32(Bhi), sBlo = smem_u32(Blo);
    float d[8][4] = {};

    uint32_t a_off = (uint32_t)(wr * 16 + ((lane >> 3) & 1) * 8 + (lane & 7)) * (PSTR * 2)
                   + (uint32_t)((lane >> 4) * 8) * 2;
    uint32_t b_roff = (uint32_t)(wc * 64 + (lane >> 4) * 8 + (lane & 7)) * (PSTR * 2);
    uint32_t b_koff = (uint32_t)(((lane >> 3) & 1) * 8) * 2;

    for (int k0 = 0; k0 < Fin; k0 += 32) {
        __syncthreads();
        // A tile: 64m x 32k (one 16B load per thread per hi/lo)
        {
            int m = t >> 2, q = t & 3;
            size_t go = (size_t)(row0 + m) * Fin + k0 + q * 8;
            *(uint4*)&Ahi[m][q * 8] = *(const uint4*)(Xhi + go);
            *(uint4*)&Alo[m][q * 8] = *(const uint4*)(Xlo + go);
        }
        // B tile: 128n x 32k
#pragma unroll
        for (int l = 0; l < 2; l++) {
            int idx = t + l * 256;
            int n = idx >> 2, q = idx & 3;
            size_t go = (size_t)n * Fin + k0 + q * 8;
            *(uint4*)&Bhi[n][q * 8] = *(const uint4*)(Wth + go);
            *(uint4*)&Blo[n][q * 8] = *(const uint4*)(Wtl + go);
        }
        __syncthreads();
#pragma unroll
        for (int s = 0; s < 2; s++) {
            unsigned ah[4], al[4];
            ldsm_x4(ah, sAhi + a_off + s * 32);
            ldsm_x4(al, sAlo + a_off + s * 32);
#pragma unroll
            for (int pp = 0; pp < 4; pp++) {
                unsigned bh[4], bl[4];
                uint32_t boff = b_roff + (uint32_t)(pp * 16) * (PSTR * 2) + b_koff + s * 32;
                ldsm_x4(bh, sBhi + boff);
                ldsm_x4(bl, sBlo + boff);
                mma_bf16(d[2 * pp],     ah, bh);
                mma_bf16(d[2 * pp + 1], ah, bh + 2);
                mma_bf16(d[2 * pp],     ah, bl);
                mma_bf16(d[2 * pp + 1], ah, bl + 2);
                mma_bf16(d[2 * pp],     al, bh);
                mma_bf16(d[2 * pp + 1], al, bh + 2);
            }
        }
    }
    int r0 = row0 + wr * 16 + (lane >> 2);
    int cbase = wc * 64 + (lane & 3) * 2;
#pragma unroll
    for (int nt = 0; nt < 8; nt++) {
        int col = cbase + nt * 8;
        *(float2*)&outp[(size_t)r0 * 128 + col] = make_float2(d[nt][0], d[nt][1]);
        *(float2*)&outp[(size_t)(r0 + 8) * 128 + col] = make_float2(d[nt][2], d[nt][3]);
    }
}

// ===========================================================================
// f1/f2
// ===========================================================================
__global__ void compute_f_kernel(const float* __restrict__ Wh, const float* __restrict__ A,
                                 float* __restrict__ f1, float* __restrict__ f2) {
    int h = blockIdx.y;
    int warp = threadIdx.x >> 5, lane = threadIdx.x & 31;
    int i = blockIdx.x * 8 + warp;
    const float* row = Wh + ((size_t)h * NN + i) * 128;
    const float* a = A + h * 256;
    float s1 = 0.f, s2 = 0.f;
#pragma unroll
    for (int d = lane; d < 128; d += 32) {
        float v = row[d];
        s1 += v * a[d];
        s2 += v * a[128 + d];
    }
#pragma unroll
    for (int o = 16; o; o >>= 1) {
        s1 += __shfl_xor_sync(0xffffffffu, s1, o);
        s2 += __shfl_xor_sync(0xffffffffu, s2, o);
    }
    if (lane == 0) {
        f1[h * NN + i] = s1;
        f2[h * NN + i] = s2;
    }
}

// ===========================================================================
// softmax stats
// ===========================================================================
__global__ void stats_kernel(const float* __restrict__ f1, const float* __restrict__ f2,
                             const unsigned* __restrict__ mask,
                             float* __restrict__ mo, float* __restrict__ sio) {
    int h = blockIdx.y;
    int rowbase = blockIdx.x * 16;
    __shared__ float f2s[NN];
    __shared__ unsigned mws[16][128];
    int t = threadIdx.x;
    for (int j = t; j < NN; j += 256) f2s[j] = f2[h * NN + j];
    for (int idx = t; idx < 16 * 128; idx += 256) {
        int r = idx >> 7, w = idx & 127;
        mws[r][w] = mask[(size_t)(rowbase + r) * 128 + w];
    }
    __syncthreads();
    int warp = t >> 5, lane = t & 31;
    for (int rr = warp; rr < 16; rr += 8) {
        int i = rowbase + rr;
        float fr = f1[h * NN + i];
        float mmax = -1e30f;
        for (int w = 0; w < 128; w++) {
            unsigned msk = mws[rr][w];
            if ((msk >> lane) & 1u) {
                float e = fr + f2s[w * 32 + lane];
                e = e > 0.f ? e : 0.2f * e;
                mmax = fmaxf(mmax, e);
            }
        }
#pragma unroll
        for (int o = 16; o; o >>= 1)
            mmax = fmaxf(mmax, __shfl_xor_sync(0xffffffffu, mmax, o));
        float s = 0.f;
        for (int w = 0; w < 128; w++) {
            unsigned msk = mws[rr][w];
            if ((msk >> lane) & 1u) {
                float e = fr + f2s[w * 32 + lane];
                e = e > 0.f ? e : 0.2f * e;
                s += __expf(e - mmax);
            }
        }
#pragma unroll
        for (int o = 16; o; o >>= 1) s += __shfl_xor_sync(0xffffffffu, s, o);
        if (lane == 0) {
            mo[h * NN + i] = mmax;
            sio[h * NN + i] = 1.f / s;
        }
    }
}

// ===========================================================================
// rowA = si*exp(f1-m), rowC = si*exp(0.2f1-m), colB = exp(f2), colD = exp(0.2f2)
// ===========================================================================
__global__ void prep_vec_kernel(const float* __restrict__ f1, const float* __restrict__ f2,
                                const float* __restrict__ mm, const float* __restrict__ si,
                                float* __restrict__ rowA, float* __restrict__ rowC,
                                float* __restrict__ colB, float* __restrict__ colD) {
    int h = blockIdx.y;
    int i = blockIdx.x * 256 + threadIdx.x;
    int idx = h * NN + i;
    float m = mm[idx], s = si[idx], a = f1[idx], b = f2[idx];
    rowA[idx] = s * __expf(a - m);
    rowC[idx] = s * __expf(0.2f * a - m);
    colB[idx] = __expf(b);
    colD[idx] = __expf(0.2f * b);
}

// ===========================================================================
// Pipelined mma.sync attention. CTA 64m x 128n, grid (64, H).
// Double-buffered B (cp.async) and P tiles; 1 barrier + wait_group per chunk.
// Dynamic smem layout (bytes):
//   P[buf][hl]: (buf*2+hl)*5120        (64 rows x 80B)   total 20480
//   B[buf][hl]: 20480+(buf*2+hl)*10240 (128 rows x 80B)  total 40960
// ===========================================================================
#define ATT_SMEM 61440

__global__ void __launch_bounds__(256)
attn_mma_kernel(const __nv_bfloat16* __restrict__ WhT_hi,
                const __nv_bfloat16* __restrict__ WhT_lo,
                const float* __restrict__ rowA, const float* __restrict__ rowC,
                const float* __restrict__ colB, const float* __restrict__ colD,
                const unsigned* __restrict__ mask,
                float* __restrict__ out, int out_stride) {
    extern __shared__ __align__(16) char smem[];
    uint32_t sb = smem_u32(smem);
    const uint32_t sP = sb;
    const uint32_t sB = sb + 20480;

    int h = blockIdx.y;
    int row0 = blockIdx.x * 64;
    int hbase = h * NN;
    int t = threadIdx.x, wid = t >> 5, lane = t & 31;
    int wr = wid & 3, wc = wid >> 2;

    const __nv_bfloat16* Whh = WhT_hi + (size_t)(h * 128) * NN;
    const __nv_bfloat16* Whl = WhT_lo + (size_t)(h * 128) * NN;

    // P-gen role
    int pr = t >> 2, kq = t & 3;
    float Ar = rowA[hbase + row0 + pr];
    float Cr = rowC[hbase + row0 + pr];
    const unsigned* mrow = mask + (size_t)(row0 + pr) * 128;
    const float* cBp = colB + hbase;
    const float* cDp = colD + hbase;

    // ldmatrix lane addresses (bytes)
    uint32_t a_off = (uint32_t)(wr * 16 + ((lane >> 3) & 1) * 8 + (lane & 7)) * (PSTR * 2)
                   + (uint32_t)((lane >> 4) * 8) * 2;
    uint32_t b_roff = (uint32_t)(wc * 64 + (lane >> 4) * 8 + (lane & 7)) * (PSTR * 2);
    uint32_t b_koff = (uint32_t)(((lane >> 3) & 1) * 8) * 2;

    float d[8][4] = {};

    // stage chunk c's B tile into buffer buf via cp.async (each thread 4x16B)
    auto stage = [&](int c, int buf) {
#pragma unroll
        for (int l = 0; l < 2; l++) {
            int idx = t + l * 256;
            int n = idx >> 2, q = idx & 3;
            size_t go = (size_t)n * NN + c * 32 + q * 8;
            cp16(sB + (uint32_t)(buf * 2 + 0) * 10240 + n * 80 + q * 16, Whh + go);
            cp16(sB + (uint32_t)(buf * 2 + 1) * 10240 + n * 80 + q * 16, Whl + go);
        }
        CP_COMMIT();
    };
    // generate P(c) into buffer buf (split bf16 hi/lo)
    auto pgen = [&](int c, int buf) {
        int kb = c * 32 + kq * 8;
        unsigned w8 = mrow[c] >> (kq * 8);
        float4 b0 = *(const float4*)(cBp + kb);
        float4 b1 = *(const float4*)(cBp + kb + 4);
        float4 d0 = *(const float4*)(cDp + kb);
        float4 d1 = *(const float4*)(cDp + kb + 4);
        float p[8];
        p[0] = (w8 & 1u)   ? fmaxf(Ar * b0.x, Cr * d0.x) : 0.f;
        p[1] = (w8 & 2u)   ? fmaxf(Ar * b0.y, Cr * d0.y) : 0.f;
        p[2] = (w8 & 4u)   ? fmaxf(Ar * b0.z, Cr * d0.z) : 0.f;
        p[3] = (w8 & 8u)   ? fmaxf(Ar * b0.w, Cr * d0.w) : 0.f;
        p[4] = (w8 & 16u)  ? fmaxf(Ar * b1.x, Cr * d1.x) : 0.f;
        p[5] = (w8 & 32u)  ? fmaxf(Ar * b1.y, Cr * d1.y) : 0.f;
        p[6] = (w8 & 64u)  ? fmaxf(Ar * b1.z, Cr * d1.z) : 0.f;
        p[7] = (w8 & 128u) ? fmaxf(Ar * b1.w, Cr * d1.w) : 0.f;
        uint4 uh, ul;
        unsigned* ph = &uh.x;
        unsigned* pl = &ul.x;
#pragma unroll
        for (int j = 0; j < 4; j++) {
            __nv_bfloat162 h2 = __floats2bfloat162_rn(p[2 * j], p[2 * j + 1]);
            float r0 = p[2 * j] - __bfloat162float(h2.x);
            float r1 = p[2 * j + 1] - __bfloat162float(h2.y);
            __nv_bfloat162 l2 = __floats2bfloat162_rn(r0, r1);
            ph[j] = *(unsigned*)&h2;
            pl[j] = *(unsigned*)&l2;
        }
        *(uint4*)(smem + (buf * 2 + 0) * 5120 + pr * 80 + kq * 16) = uh;
        *(uint4*)(smem + (buf * 2 + 1) * 5120 + pr * 80 + kq * 16) = ul;
    };

    // prologue
    stage(0, 0);
    pgen(0, 0);

    for (int c = 0; c < 128; c++) {
        int buf = c & 1;
        CP_WAIT0();          // B(c) arrived (this thread's group)
        __syncthreads();     // publish B(c), P(c); all done reading buf^1
        if (c + 1 < 128) {
            stage(c + 1, buf ^ 1);   // overlaps with mma below
            pgen(c + 1, buf ^ 1);
        }
        uint32_t pH = sP + (uint32_t)(buf * 2 + 0) * 5120;
        uint32_t pL = sP + (uint32_t)(buf * 2 + 1) * 5120;
        uint32_t bH = sB + (uint32_t)(buf * 2 + 0) * 10240;
        uint32_t bL = sB + (uint32_t)(buf * 2 + 1) * 10240;
#pragma unroll
        for (int s = 0; s < 2; s++) {
            unsigned ah[4], al[4];
            ldsm_x4(ah, pH + a_off + s * 32);
            ldsm_x4(al, pL + a_off + s * 32);
#pragma unroll
            for (int pp = 0; pp < 4; pp++) {
                unsigned bh[4], bl[4];
                uint32_t boff = b_roff + (uint32_t)(pp * 16) * (PSTR * 2) + b_koff + s * 32;
                ldsm_x4(bh, bH + boff);
                ldsm_x4(bl, bL + boff);
                mma_bf16(d[2 * pp],     ah, bh);
                mma_bf16(d[2 * pp + 1], ah, bh + 2);
                mma_bf16(d[2 * pp],     ah, bl);
                mma_bf16(d[2 * pp + 1], ah, bl + 2);
                mma_bf16(d[2 * pp],     al, bh);
                mma_bf16(d[2 * pp + 1], al, bh + 2);
            }
        }
    }

    // epilogue: elu + write
    int r0 = row0 + wr * 16 + (lane >> 2);
    int cbase = h * 128 + wc * 64 + (lane & 3) * 2;
#pragma unroll
    for (int nt = 0; nt < 8; nt++) {
        int col = cbase + nt * 8;
        float v0 = d[nt][0], v1 = d[nt][1], v2 = d[nt][2], v3 = d[nt][3];
        v0 = v0 > 0.f ? v0 : expm1f(v0);
        v1 = v1 > 0.f ? v1 : expm1f(v1);
        v2 = v2 > 0.f ? v2 : expm1f(v2);
        v3 = v3 > 0.f ? v3 : expm1f(v3);
        *(float2*)&out[(size_t)r0 * out_stride + col] = make_float2(v0, v1);
        *(float2*)&out[(size_t)(r0 + 8) * out_stride + col] = make_float2(v2, v3);
    }
}

// ===========================================================================
extern "C" void kernel_launch(void* const* d_in, const int* in_sizes, int n_in,
                              void* d_out, int out_size) {
    const int* head = (const int*)d_in[0];
    const int* rel = (const int*)d_in[1];
    const float* adj = (const float*)d_in[2];
    const float* ee = (const float*)d_in[3];
    const float* re = (const float*)d_in[4];
    const float* W0 = (const float*)d_in[5];
    const float* a0 = (const float*)d_in[6];
    const float* Wm = (const float*)d_in[7];
    const float* am = (const float*)d_in[8];
    const float* Wo = (const float*)d_in[9];
    const float* ao = (const float*)d_in[10];
    float* out = (float*)d_out;

    float *X0, *X1, *Wh, *f1, *f2, *mv, *si, *rA, *rC, *cB, *cD;
    __nv_bfloat16 *WhTh, *WhTl, *Xhi, *Xlo, *Wth, *Wtl;
    unsigned* mask;
    cudaGetSymbolAddress((void**)&X0, g_X0);
    cudaGetSymbolAddress((void**)&X1, g_X1);
    cudaGetSymbolAddress((void**)&Wh, g_Wh);
    cudaGetSymbolAddress((void**)&f1, g_f1);
    cudaGetSymbolAddress((void**)&f2, g_f2);
    cudaGetSymbolAddress((void**)&mv, g_m);
    cudaGetSymbolAddress((void**)&si, g_si);
    cudaGetSymbolAddress((void**)&rA, g_rowA);
    cudaGetSymbolAddress((void**)&rC, g_rowC);
    cudaGetSymbolAddress((void**)&cB, g_colB);
    cudaGetSymbolAddress((void**)&cD, g_colD);
    cudaGetSymbolAddress((void**)&WhTh, g_WhT_hi);
    cudaGetSymbolAddress((void**)&WhTl, g_WhT_lo);
    cudaGetSymbolAddress((void**)&Xhi, g_Xhi);
    cudaGetSymbolAddress((void**)&Xlo, g_Xlo);
    cudaGetSymbolAddress((void**)&Wth, g_Wt_hi);
    cudaGetSymbolAddress((void**)&Wtl, g_Wt_lo);
    cudaGetSymbolAddress((void**)&mask, g_mask);

    cudaFuncSetAttribute(attn_mma_kernel, cudaFuncAttributeMaxDynamicSharedMemorySize, ATT_SMEM);

    build_mask_kernel<<<NN, 256>>>(adj, mask);
    hrc_kernel<<<NN, 128>>>(head, rel, ee, re, out + (size_t)NN * 128);

    // ---- layer 0: Fin = 128, X = entity_emb ----
    split_kernel<<<(NN * 128 + 255) / 256, 256>>>(ee, Xhi, Xlo, NN * 128);
    wt_split_kernel<<<dim3(4, 4, HH), 256>>>(W0, Wth, Wtl, 128);
    gemm_mma_kernel<<<dim3(64, HH), 256>>>(Xhi, Xlo, Wth, Wtl, Wh, 128);
    compute_f_kernel<<<dim3(512, HH), 256>>>(Wh, a0, f1, f2);
    stats_kernel<<<dim3(256, HH), 256>>>(f1, f2, mask, mv, si);
    prep_vec_kernel<<<dim3(16, HH), 256>>>(f1, f2, mv, si, rA, rC, cB, cD);
    wt_split_kernel<<<dim3(128, 4, HH), 256>>>(Wh, WhTh, WhTl, NN);
    attn_mma_kernel<<<dim3(64, HH), 256, ATT_SMEM>>>(WhTh, WhTl, rA, rC, cB, cD, mask, X0, 512);

    // ---- 9 middle layers: Fin = 512 ----
    float* cur = X0;
    float* nxt = X1;
    for (int l = 0; l < NMID; l++) {
        split_kernel<<<(NN * 512 + 255) / 256, 256>>>(cur, Xhi, Xlo, NN * 512);
        wt_split_kernel<<<dim3(16, 4, HH), 256>>>(Wm + (size_t)l * HH * 512 * 128, Wth, Wtl, 512);
        gemm_mma_kernel<<<dim3(64, HH), 256>>>(Xhi, Xlo, Wth, Wtl, Wh, 512);
        compute_f_kernel<<<dim3(512, HH), 256>>>(Wh, am + (size_t)l * HH * 256, f1, f2);
        stats_kernel<<<dim3(256, HH), 256>>>(f1, f2, mask, mv, si);
        prep_vec_kernel<<<dim3(16, HH), 256>>>(f1, f2, mv, si, rA, rC, cB, cD);
        wt_split_kernel<<<dim3(128, 4, HH), 256>>>(Wh, WhTh, WhTl, NN);
        attn_mma_kernel<<<dim3(64, HH), 256, ATT_SMEM>>>(WhTh, WhTl, rA, rC, cB, cD, mask, nxt, 512);
        float* tmp = cur; cur = nxt; nxt = tmp;
    }

    // ---- output layer: 1 head, Fin = 512 ----
    split_kernel<<<(NN * 512 + 255) / 256, 256>>>(cur, Xhi, Xlo, NN * 512);
    wt_split_kernel<<<dim3(16, 4, 1), 256>>>(Wo, Wth, Wtl, 512);
    gemm_mma_kernel<<<dim3(64, 1), 256>>>(Xhi, Xlo, Wth, Wtl, Wh, 512);
    compute_f_kernel<<<dim3(512, 1), 256>>>(Wh, ao, f1, f2);
    stats_kernel<<<dim3(256, 1), 256>>>(f1, f2, mask, mv, si);
    prep_vec_kernel<<<dim3(16, 1), 256>>>(f1, f2, mv, si, rA, rC, cB, cD);
    wt_split_kernel<<<dim3(128, 4, 1), 256>>>(Wh, WhTh, WhTl, NN);
    attn_mma_kernel<<<dim3(64, 1), 256, ATT_SMEM>>>(WhTh, WhTl, rA, rC, cB, cD, mask, out, 128);
}